// round 4
// baseline (speedup 1.0000x reference)
#include <cuda_runtime.h>
#include <cuda_bf16.h>
#include <math.h>

#define B_N   4096
#define INDIM 100
#define NCLS  4
#define OC    16
#define INITD 64
#define PC    32
#define TT    16
#define LVS   32
#define DD    164
#define DP    176
#define MM    33
#define JJ    8448      /* MM*OC*TT */
#define EPS_  1e-5f
#define PREDSZ (B_N*NCLS)

// ---------------- device scratch ----------------
__device__ float  g_f[B_N*DP];
__device__ float2 g_stats[B_N*MM];            // {mu, rstd}
__device__ float  g_W2T[DP*JJ];               // [d][j]
__device__ float  g_Aj[JJ];
__device__ float  g_Cj[JJ];
__device__ float  g_priors[(size_t)B_N*JJ];   // 138 MB
__device__ float  g_lh[LVS*TT];
__device__ float  g_fc1m[3*32*64];
__device__ float  g_fc2m[3*64*80];
__device__ float  g_hsel[B_N*64];
__device__ float  g_hp1[B_N*96];
__device__ float  g_x2[B_N*80];
__device__ float  g_hp2[B_N*192];
__device__ float2 g_gbn1[16*96];
__device__ float2 g_gbn2[16*192];

__device__ __forceinline__ float wsum(float v){
#pragma unroll
    for (int o=16;o>0;o>>=1) v += __shfl_xor_sync(0xffffffffu, v, o);
    return v;
}
__device__ __forceinline__ float wmax(float v){
#pragma unroll
    for (int o=16;o>0;o>>=1) v = fmaxf(v, __shfl_xor_sync(0xffffffffu, v, o));
    return v;
}

// ---------------- entmax over route_w + fold into W2T/A/C ----------------
__global__ __launch_bounds__(128) void k_route(const float* __restrict__ rw,
                                               const float* __restrict__ prim,
                                               const float* __restrict__ lng,
                                               const float* __restrict__ lnb){
    int warp = (blockIdx.x*blockDim.x + threadIdx.x) >> 5;
    int lane = threadIdx.x & 31;
    if (warp >= JJ) return;
    int m = warp >> 8, nt = warp & 255, n = nt >> 4, t = nt & 15;
    const float* base = rw + ((size_t)(m*OC + n)*DD)*TT + t;
    float v[6];
#pragma unroll
    for (int k=0;k<6;k++){
        int d = lane + 32*k;
        v[k] = (d < DD) ? base[(size_t)d*TT] : -1e30f;
    }
    float mx = -1e30f;
#pragma unroll
    for (int k=0;k<6;k++) mx = fmaxf(mx, v[k]);
    mx = wmax(mx);
    float xt[6];
#pragma unroll
    for (int k=0;k<6;k++) xt[k] = (v[k] - mx)*0.5f;
    float lo = -1.f, hi = 0.f;
    for (int it=0; it<30; it++){
        float mid = 0.5f*(lo+hi);
        float s = 0.f;
#pragma unroll
        for (int k=0;k<6;k++){
            float r = xt[k] - mid;
            if (r > 0.f) s += r*r;
        }
        s = wsum(s);
        if (s > 1.f) lo = mid; else hi = mid;
    }
    float tau = 0.5f*(lo+hi);
    float asum = 0.f, csum = 0.f;
#pragma unroll
    for (int k=0;k<6;k++){
        int d = lane + 32*k;
        if (d < DD){
            float r = xt[k] - tau;
            float p = (r > 0.f) ? r*r : 0.f;
            float gg = lng[d];
            float P  = (m < 32) ? prim[d*PC + m] : 1.f;
            g_W2T[(size_t)d*JJ + warp] = p*P*gg;
            asum += p*gg;
            csum += p*lnb[d];
        }
    }
    asum = wsum(asum); csum = wsum(csum);
    if (lane == 0){ g_Aj[warp] = asum; g_Cj[warp] = csum; }
}

__global__ void k_zeropad(){
    int i = blockIdx.x*blockDim.x + threadIdx.x;
    if (i < 12*JJ) g_W2T[(size_t)(DD + i/JJ)*JJ + (i % JJ)] = 0.f;
}

// ---------------- small constants ----------------
__device__ float entmax_tau_serial(const float* x, int n){
    float mx = -1e30f;
    for (int i=0;i<n;i++) mx = fmaxf(mx, x[i]);
    float lo = -1.f, hi = 0.f;
    for (int it=0; it<30; it++){
        float mid = 0.5f*(lo+hi);
        float s = 0.f;
        for (int i=0;i<n;i++){
            float r = (x[i]-mx)*0.5f - mid;
            if (r > 0.f) s += r*r;
        }
        if (s > 1.f) lo = mid; else hi = mid;
    }
    return 0.5f*(lo+hi);
}

__global__ __launch_bounds__(256) void k_const2(const float* __restrict__ leaves,
                                                const float* __restrict__ m1w,
                                                const float* __restrict__ fc1w,
                                                const float* __restrict__ m2w,
                                                const float* __restrict__ fc2w){
    __shared__ float mask1[3*64];
    __shared__ float mask2[3*80];
    int tid = threadIdx.x;
    if (tid < 32){
        float s = 0.f;
        for (int t=0;t<TT;t++){ float v = leaves[tid*TT+t]; s += v*v; }
        float inv = 1.f / fmaxf(sqrtf(s), 1e-12f);
        for (int t=0;t<TT;t++) g_lh[tid*TT+t] = leaves[tid*TT+t]*inv;
    }
    if (tid < 3){
        const float* row = m1w + tid*64;
        float tau = entmax_tau_serial(row, 64);
        float mx = -1e30f;
        for (int i=0;i<64;i++) mx = fmaxf(mx, row[i]);
        for (int i=0;i<64;i++){
            float r = (row[i]-mx)*0.5f - tau;
            mask1[tid*64+i] = (r > 0.f) ? r*r : 0.f;
        }
    }
    if (tid >= 3 && tid < 6){
        int p = tid-3;
        const float* row = m2w + p*80;
        float tau = entmax_tau_serial(row, 80);
        float mx = -1e30f;
        for (int i=0;i<80;i++) mx = fmaxf(mx, row[i]);
        for (int i=0;i<80;i++){
            float r = (row[i]-mx)*0.5f - tau;
            mask2[p*80+i] = (r > 0.f) ? r*r : 0.f;
        }
    }
    __syncthreads();
    for (int i=tid; i<3*32*64; i+=256){
        int p = i/2048, d = i & 63;
        g_fc1m[i] = fc1w[i]*mask1[p*64+d];
    }
    for (int i=tid; i<3*64*80; i+=256){
        int p = i/5120, d = i % 80;
        g_fc2m[i] = fc2w[i]*mask2[p*80+d];
    }
}

// ---------------- f = [x, x@init_w^T+b] + per-(b,m) LN stats ----------------
__global__ __launch_bounds__(128) void k_f(const float* __restrict__ x,
                                           const float* __restrict__ iw,
                                           const float* __restrict__ ib,
                                           const float* __restrict__ prim){
    __shared__ float sx[INDIM];
    __shared__ float sf[DD];
    int b = blockIdx.x, t = threadIdx.x;
    if (t < INDIM) sx[t] = x[(size_t)b*INDIM + t];
    __syncthreads();
    if (t < INITD){
        float a = ib[t];
        const float* wr = iw + t*INDIM;
        for (int d=0; d<INDIM; d++) a += sx[d]*wr[d];
        sf[INDIM+t] = a;
        g_f[(size_t)b*DP + INDIM + t] = a;
    }
    if (t < INDIM){
        sf[t] = sx[t];
        g_f[(size_t)b*DP + t] = sx[t];
    }
    if (t >= 112 && t < 124) g_f[(size_t)b*DP + DD + (t-112)] = 0.f;
    __syncthreads();
    if (t < MM){
        float s = 0.f, s2 = 0.f;
        if (t < 32){
            for (int d=0; d<DD; d++){
                float c = sf[d]*prim[d*PC + t];
                s += c; s2 += c*c;
            }
        } else {
            for (int d=0; d<DD; d++){ float c = sf[d]; s += c; s2 += c*c; }
        }
        float mu = s*(1.f/DD);
        float var = s2*(1.f/DD) - mu*mu;
        float r = rsqrtf(fmaxf(var, 0.f) + EPS_);
        g_stats[b*MM + t] = make_float2(mu, r);
    }
}

// ---------------- GEMM: priors = rstd*(f@W2) - rstd*mu*A + C ----------------
__global__ __launch_bounds__(256) void k_gemm(){
    __shared__ float As[2][16][128];
    __shared__ float Bs[2][16][128];
    const int tid = threadIdx.x;
    const int j0 = blockIdx.x*128, b0 = blockIdx.y*128;
    const int ty = tid >> 4, tx = tid & 15;
    const int e1 = tid + 256;
    float acc[8][8];
#pragma unroll
    for (int i=0;i<8;i++)
#pragma unroll
        for (int j=0;j<8;j++) acc[i][j] = 0.f;

    float4 ra0, ra1, rb0, rb1;
    ra0 = *(const float4*)&g_f[(size_t)(b0 + (tid>>2))*DP + (tid&3)*4];
    ra1 = *(const float4*)&g_f[(size_t)(b0 + (e1>>2))*DP + (e1&3)*4];
    rb0 = *(const float4*)&g_W2T[(size_t)(tid>>5)*JJ + j0 + (tid&31)*4];
    rb1 = *(const float4*)&g_W2T[(size_t)(e1>>5)*JJ + j0 + (e1&31)*4];
    {
        int r0 = tid>>2, c0 = (tid&3)*4, r1 = e1>>2, c1 = (e1&3)*4;
        As[0][c0+0][r0]=ra0.x; As[0][c0+1][r0]=ra0.y; As[0][c0+2][r0]=ra0.z; As[0][c0+3][r0]=ra0.w;
        As[0][c1+0][r1]=ra1.x; As[0][c1+1][r1]=ra1.y; As[0][c1+2][r1]=ra1.z; As[0][c1+3][r1]=ra1.w;
        *(float4*)&Bs[0][tid>>5][(tid&31)*4] = rb0;
        *(float4*)&Bs[0][e1>>5][(e1&31)*4]   = rb1;
    }
    __syncthreads();

#pragma unroll 1
    for (int kt=0; kt<11; kt++){
        int cur = kt & 1;
        if (kt < 10){
            int k0 = (kt+1)*16;
            ra0 = *(const float4*)&g_f[(size_t)(b0 + (tid>>2))*DP + k0 + (tid&3)*4];
            ra1 = *(const float4*)&g_f[(size_t)(b0 + (e1>>2))*DP + k0 + (e1&3)*4];
            rb0 = *(const float4*)&g_W2T[(size_t)(k0 + (tid>>5))*JJ + j0 + (tid&31)*4];
            rb1 = *(const float4*)&g_W2T[(size_t)(k0 + (e1>>5))*JJ + j0 + (e1&31)*4];
        }
#pragma unroll
        for (int kk=0; kk<16; kk++){
            float4 a0 = *(float4*)&As[cur][kk][ty*8];
            float4 a1 = *(float4*)&As[cur][kk][ty*8+4];
            float4 bb0 = *(float4*)&Bs[cur][kk][tx*8];
            float4 bb1 = *(float4*)&Bs[cur][kk][tx*8+4];
            float a[8] = {a0.x,a0.y,a0.z,a0.w,a1.x,a1.y,a1.z,a1.w};
            float bv[8] = {bb0.x,bb0.y,bb0.z,bb0.w,bb1.x,bb1.y,bb1.z,bb1.w};
#pragma unroll
            for (int i=0;i<8;i++)
#pragma unroll
                for (int j=0;j<8;j++) acc[i][j] += a[i]*bv[j];
        }
        if (kt < 10){
            int nb = cur ^ 1;
            int r0 = tid>>2, c0 = (tid&3)*4, r1 = e1>>2, c1 = (e1&3)*4;
            As[nb][c0+0][r0]=ra0.x; As[nb][c0+1][r0]=ra0.y; As[nb][c0+2][r0]=ra0.z; As[nb][c0+3][r0]=ra0.w;
            As[nb][c1+0][r1]=ra1.x; As[nb][c1+1][r1]=ra1.y; As[nb][c1+2][r1]=ra1.z; As[nb][c1+3][r1]=ra1.w;
            *(float4*)&Bs[nb][tid>>5][(tid&31)*4] = rb0;
            *(float4*)&Bs[nb][e1>>5][(e1&31)*4]   = rb1;
            __syncthreads();
        }
    }

    const int m = j0 >> 8;
    float aj[8], cj[8];
#pragma unroll
    for (int j=0;j<8;j++){
        aj[j] = g_Aj[j0 + tx*8 + j];
        cj[j] = g_Cj[j0 + tx*8 + j];
    }
#pragma unroll
    for (int i=0;i<8;i++){
        int b = b0 + ty*8 + i;
        float2 st = g_stats[b*MM + m];
        float rs = st.y, rm = st.y*st.x;
        float o[8];
#pragma unroll
        for (int j=0;j<8;j++) o[j] = rs*acc[i][j] - rm*aj[j] + cj[j];
        *(float4*)&g_priors[(size_t)b*JJ + j0 + tx*8]     = make_float4(o[0],o[1],o[2],o[3]);
        *(float4*)&g_priors[(size_t)b*JJ + j0 + tx*8 + 4] = make_float4(o[4],o[5],o[6],o[7]);
    }
}

// ---------------- per-b routing reduce ----------------
__global__ __launch_bounds__(256) void k_reduce(const float* __restrict__ y,
                                                const float* __restrict__ thr,
                                                const float* __restrict__ clg,
                                                const float* __restrict__ clb,
                                                float* __restrict__ out){
    extern __shared__ float dsm[];
    float* sp = dsm;              // 8448
    float* sv = dsm + 8448;       // 528*33
    __shared__ float vb[16*33];
    __shared__ float wg[528];
    __shared__ float lhs[32*17];
    __shared__ float th2[528];
    __shared__ float sh[256];
    __shared__ float sy[4];
    __shared__ float snorm[16];
    __shared__ float sclg[16], sclb[16];

    int b = blockIdx.x, tid = threadIdx.x;
    {
        const float4* prow = (const float4*)(g_priors + (size_t)b*JJ);
        float4* spd = (float4*)sp;
        for (int i=tid; i<JJ/4; i+=256) spd[i] = prow[i];
    }
    for (int i=tid; i<512; i+=256) lhs[(i>>4)*17 + (i&15)] = g_lh[i];
    for (int i=tid; i<528; i+=256){ float v = thr[i]; th2[i] = v*v; }
    if (tid < 4) sy[tid] = y[(size_t)b*4 + tid];
    if (tid < 16){ sclg[tid] = clg[tid]; sclb[tid] = clb[tid]; }
    __syncthreads();

    for (int i=tid; i<16896; i+=256){
        int mn = i >> 5, l = i & 31;
        const float* pp = sp + mn*16;
        const float* ll = lhs + l*17;
        float a = 0.f;
#pragma unroll
        for (int t=0;t<16;t++) a += pp[t]*ll[t];
        sv[mn*33 + l] = 1.f/(1.f + __expf(-a));
    }
    __syncthreads();
    for (int i=tid; i<512; i+=256){
        int n = i >> 5, l = i & 31;
        float a = 0.f;
        for (int m=0;m<MM;m++) a += sv[(m*16+n)*33 + l];
        vb[n*33 + l] = a*(1.f/33.f);
    }
    __syncthreads();
    for (int i=tid; i<528; i+=256){
        int n = i & 15;
        float a = 0.f;
        for (int l=0;l<32;l++){
            float d = sv[i*33 + l] - vb[n*33 + l];
            a += d*d;
        }
        float w = th2[i] - a*(1.f/32.f);
        wg[i] = (w > 0.f) ? w : 0.f;
    }
    __syncthreads();
    if (tid < 16){
        int n = tid;
        float mx = -1e30f;
        for (int m=0;m<MM;m++) mx = fmaxf(mx, wg[m*16+n]);
        float s = 0.f;
        for (int m=0;m<MM;m++){ float e = __expf(wg[m*16+n]-mx); wg[m*16+n] = e; s += e; }
        float inv = 1.f/s;
        for (int m=0;m<MM;m++) wg[m*16+n] *= inv;
    }
    __syncthreads();
    if (tid < 256){
        int n = tid >> 4, t = tid & 15;
        float a = 0.f;
        for (int m=0;m<MM;m++) a += wg[m*16+n]*sp[(m*16+n)*16 + t];
        sh[tid] = a;
    }
    __syncthreads();
    if (tid < 16){
        int n = tid;
        float s = 0.f, s2 = 0.f;
        for (int t=0;t<16;t++){ float v = sh[n*16+t]; s += v; s2 += v*v; }
        float mu = s*(1.f/16.f);
        float var = s2*(1.f/16.f) - mu*mu;
        float r = rsqrtf(fmaxf(var,0.f) + EPS_);
        float nn = 0.f;
        for (int t=0;t<16;t++){
            float h = (sh[n*16+t]-mu)*r*sclg[t] + sclb[t];
            sh[n*16+t] = h;
            nn += h*h;
        }
        snorm[n] = sqrtf(nn);
    }
    __syncthreads();
    if (tid < 4)
        out[(size_t)b*4 + tid] = snorm[tid*4]+snorm[tid*4+1]+snorm[tid*4+2]+snorm[tid*4+3];
    if (tid < 64){
        int s = tid >> 4, t = tid & 15;
        float a = 0.f;
#pragma unroll
        for (int c=0;c<4;c++) a += sy[c]*sh[(s*4+c)*16 + t];
        g_hsel[(size_t)b*64 + tid] = a;
    }
}

// ---------------- decoder ----------------
__global__ __launch_bounds__(256) void k_dec1(){
    __shared__ float w[3*32*64];
    __shared__ float hs[32*65];
    int b0 = blockIdx.x*32, tid = threadIdx.x;
    for (int i=tid; i<6144; i+=256) w[i] = g_fc1m[i];
    for (int i=tid; i<2048; i+=256){
        int bl = i >> 6, d = i & 63;
        hs[bl*65 + d] = g_hsel[(size_t)(b0+bl)*64 + d];
    }
    __syncthreads();
    for (int idx=tid; idx<3072; idx+=256){
        int po = idx >> 5, bl = idx & 31;
        const float* wr = w + po*64;
        const float* hr = hs + bl*65;
        float a = 0.f;
#pragma unroll
        for (int d=0; d<64; d++) a += hr[d]*wr[d];
        g_hp1[(size_t)(b0+bl)*96 + po] = a;
    }
}

// GBN stats: reference device globals directly (NOT as host-passed args)
__global__ void k_gbn1(const float* __restrict__ bg, const float* __restrict__ bb){
    int g = blockIdx.x, k = threadIdx.x;
    if (k >= 96) return;
    float s = 0.f, s2 = 0.f;
    const float* p = g_hp1 + (size_t)g*256*96 + k;
    for (int i=0;i<256;i++){ float v = p[(size_t)i*96]; s += v; s2 += v*v; }
    float mu = s*(1.f/256.f);
    float var = s2*(1.f/256.f) - mu*mu;
    float r = rsqrtf(fmaxf(var,0.f) + EPS_);
    float a = bg[k]*r;
    g_gbn1[g*96 + k] = make_float2(a, bb[k] - mu*a);
}

__global__ void k_gbn2(const float* __restrict__ bg, const float* __restrict__ bb){
    int g = blockIdx.x, k = threadIdx.x;
    if (k >= 192) return;
    float s = 0.f, s2 = 0.f;
    const float* p = g_hp2 + (size_t)g*256*192 + k;
    for (int i=0;i<256;i++){ float v = p[(size_t)i*192]; s += v; s2 += v*v; }
    float mu = s*(1.f/256.f);
    float var = s2*(1.f/256.f) - mu*mu;
    float r = rsqrtf(fmaxf(var,0.f) + EPS_);
    float a = bg[k]*r;
    g_gbn2[g*192 + k] = make_float2(a, bb[k] - mu*a);
}

__global__ void k_glu1(){
    int idx = blockIdx.x*256 + threadIdx.x;
    if (idx >= B_N*80) return;
    int b = idx/80, o = idx - b*80;
    if (o < 64){
        g_x2[idx] = g_hsel[(size_t)b*64 + o];
    } else {
        int oo = o - 64, g = b >> 8;
        float a = 0.f;
#pragma unroll
        for (int p=0;p<3;p++){
            int k1 = p*32 + oo, k2 = k1 + 16;
            float2 t1 = g_gbn1[g*96 + k1], t2 = g_gbn1[g*96 + k2];
            float x1 = g_hp1[(size_t)b*96 + k1]*t1.x + t1.y;
            float x2 = g_hp1[(size_t)b*96 + k2]*t2.x + t2.y;
            float sg = 1.f/(1.f + __expf(-x1));
            a += fmaxf(sg*x2, 0.f);
        }
        g_x2[idx] = a;
    }
}

__global__ __launch_bounds__(256) void k_dec2(){
    extern __shared__ float dsm2[];
    float* w  = dsm2;           // 15360
    float* hs = dsm2 + 15360;   // 32*81
    int b0 = blockIdx.x*32, tid = threadIdx.x;
    for (int i=tid; i<15360; i+=256) w[i] = g_fc2m[i];
    for (int i=tid; i<2560; i+=256){
        int bl = i/80, d = i - bl*80;
        hs[bl*81 + d] = g_x2[(size_t)(b0+bl)*80 + d];
    }
    __syncthreads();
    for (int idx=tid; idx<6144; idx+=256){
        int po = idx >> 5, bl = idx & 31;
        const float* wr = w + po*80;
        const float* hr = hs + bl*81;
        float a = 0.f;
#pragma unroll
        for (int d=0; d<80; d++) a += hr[d]*wr[d];
        g_hp2[(size_t)(b0+bl)*192 + po] = a;
    }
}

__global__ __launch_bounds__(256) void k_glu2rec(const float* __restrict__ dw,
                                                 const float* __restrict__ db,
                                                 float* __restrict__ out){
    __shared__ float so2[8*33];
    int b0 = blockIdx.x*8, tid = threadIdx.x;
    {
        int bl = tid >> 5, o = tid & 31;
        int b = b0 + bl, g = b >> 8;
        float a = 0.f;
#pragma unroll
        for (int p=0;p<3;p++){
            int k1 = p*64 + o, k2 = k1 + 32;
            float2 t1 = g_gbn2[g*192 + k1], t2 = g_gbn2[g*192 + k2];
            float x1 = g_hp2[(size_t)b*192 + k1]*t1.x + t1.y;
            float x2 = g_hp2[(size_t)b*192 + k2]*t2.x + t2.y;
            float sg = 1.f/(1.f + __expf(-x1));
            a += fmaxf(sg*x2, 0.f);
        }
        so2[bl*33 + o] = a;
    }
    __syncthreads();
    for (int i=tid; i<800; i+=256){
        int bl = i/100, o = i - bl*100;
        float a = db[o];
        const float* wr = dw + o*32;
        const float* sr = so2 + bl*33;
#pragma unroll
        for (int k=0;k<32;k++) a += sr[k]*wr[k];
        out[PREDSZ + (size_t)(b0+bl)*100 + o] = a;
    }
}

// ---------------- launcher ----------------
extern "C" void kernel_launch(void* const* d_in, const int* in_sizes, int n_in,
                              void* d_out, int out_size){
    const float* x      = (const float*)d_in[0];
    const float* y      = (const float*)d_in[1];
    const float* init_w = (const float*)d_in[2];
    const float* init_b = (const float*)d_in[3];
    const float* lng    = (const float*)d_in[4];
    const float* lnb    = (const float*)d_in[5];
    const float* prim   = (const float*)d_in[6];
    const float* routew = (const float*)d_in[7];
    const float* thr    = (const float*)d_in[8];
    const float* leaves = (const float*)d_in[9];
    const float* clg    = (const float*)d_in[10];
    const float* clb    = (const float*)d_in[11];
    const float* m1w    = (const float*)d_in[12];
    const float* fc1w   = (const float*)d_in[13];
    const float* bn1g   = (const float*)d_in[15];
    const float* bn1b   = (const float*)d_in[16];
    const float* m2w    = (const float*)d_in[17];
    const float* fc2w   = (const float*)d_in[18];
    const float* bn2g   = (const float*)d_in[20];
    const float* bn2b   = (const float*)d_in[21];
    const float* decw   = (const float*)d_in[22];
    const float* decb   = (const float*)d_in[23];
    float* out = (float*)d_out;

    cudaFuncSetAttribute(k_reduce, cudaFuncAttributeMaxDynamicSharedMemorySize, (8448+528*33)*4);
    cudaFuncSetAttribute(k_dec2,  cudaFuncAttributeMaxDynamicSharedMemorySize, (15360+32*81)*4);

    k_route<<<2112, 128>>>(routew, prim, lng, lnb);
    k_zeropad<<<(12*JJ+1023)/1024, 1024>>>();
    k_const2<<<1, 256>>>(leaves, m1w, fc1w, m2w, fc2w);
    k_f<<<B_N, 128>>>(x, init_w, init_b, prim);
    {
        dim3 grid(JJ/128, B_N/128);
        k_gemm<<<grid, 256>>>();
    }
    k_reduce<<<B_N, 256, (8448+528*33)*4>>>(y, thr, clg, clb, out);
    k_dec1<<<B_N/32, 256>>>();
    k_gbn1<<<16, 96>>>(bn1g, bn1b);
    k_glu1<<<(B_N*80+255)/256, 256>>>();
    k_dec2<<<B_N/32, 256, (15360+32*81)*4>>>();
    k_gbn2<<<16, 192>>>(bn2g, bn2b);
    k_glu2rec<<<B_N/8, 256>>>(decw, decb, out);
}